// round 9
// baseline (speedup 1.0000x reference)
#include <cuda_runtime.h>
#include <cuda_fp16.h>
#include <math.h>
#include <stdint.h>

#define H    3072
#define NH   24
#define HD   128
#define MLPD 12288
#define LT   512
#define LI   1024
#define L    1536
#define QKV3 9216
#define MOD6 18432

#define ROWB   144                  // bytes per smem row (64B*2 data + pad)
#define ABUF   (128 * ROWB)         // 18432 B per operand per stage
#define STAGEB (2 * ABUF)           // A+B per stage
#define STAGES 3
#define DSMEM  (STAGES * STAGEB)    // 110592 B

// ---------------- scratch (device globals) ----------------
__device__ float g_mod_img[MOD6];
__device__ float g_mod_txt[MOD6];
__device__ float g_res2[(size_t)L * H];
__device__ __align__(16) __half g_qkvh[(size_t)L * QKV3];
__device__ __align__(16) __half g_xmod[(size_t)L * H];
__device__ __align__(16) __half g_q   [(size_t)NH * L * HD];
__device__ __align__(16) __half g_k   [(size_t)NH * L * HD];
__device__ __align__(16) __half g_v   [(size_t)NH * HD * L];   // V^T: [h][d][l]
__device__ __align__(16) __half g_S   [(size_t)NH * L * L];
__device__ __align__(16) __half g_attn[(size_t)L * H];
__device__ __align__(16) __half g_hbuf[(size_t)L * H];
__device__ __align__(16) __half g_fc1 [(size_t)L * MLPD];
// transposed half weights [N][K]
__device__ __align__(16) __half g_qkvw_t [(size_t)QKV3 * H];
__device__ __align__(16) __half g_qkvcw_t[(size_t)QKV3 * H];
__device__ __align__(16) __half g_outw_t [(size_t)H * H];
__device__ __align__(16) __half g_outcw_t[(size_t)H * H];
__device__ __align__(16) __half g_fc1w_t [(size_t)MLPD * H];
__device__ __align__(16) __half g_fc1cw_t[(size_t)MLPD * H];
__device__ __align__(16) __half g_fc2w_t [(size_t)H * MLPD];
__device__ __align__(16) __half g_fc2cw_t[(size_t)H * MLPD];

// ---------------- ptx helpers ----------------
__device__ __forceinline__ uint32_t smem_u32(const void* p) {
    uint32_t a;
    asm("{ .reg .u64 t; cvta.to.shared.u64 t, %1; cvt.u32.u64 %0, t; }" : "=r"(a) : "l"(p));
    return a;
}
__device__ __forceinline__ void cp16(uint32_t dst, const void* src) {
    asm volatile("cp.async.cg.shared.global [%0], [%1], 16;" :: "r"(dst), "l"(src));
}
__device__ __forceinline__ void cp_commit() { asm volatile("cp.async.commit_group;"); }
__device__ __forceinline__ void cp_wait1()  { asm volatile("cp.async.wait_group 1;"); }
__device__ __forceinline__ void ldm4(unsigned* r, uint32_t a) {
    asm volatile("ldmatrix.sync.aligned.m8n8.x4.shared.b16 {%0,%1,%2,%3}, [%4];"
                 : "=r"(r[0]), "=r"(r[1]), "=r"(r[2]), "=r"(r[3]) : "r"(a));
}
__device__ __forceinline__ void mma_f16(float* c, const unsigned* a, const unsigned* b) {
    asm volatile(
        "mma.sync.aligned.m16n8k16.row.col.f32.f16.f16.f32 "
        "{%0,%1,%2,%3}, {%4,%5,%6,%7}, {%8,%9}, {%0,%1,%2,%3};\n"
        : "+f"(c[0]), "+f"(c[1]), "+f"(c[2]), "+f"(c[3])
        : "r"(a[0]), "r"(a[1]), "r"(a[2]), "r"(a[3]), "r"(b[0]), "r"(b[1]));
}
__device__ __forceinline__ float gelu_tanh(float x) {
    return 0.5f * x * (1.f + tanhf(0.7978845608028654f * (x + 0.044715f * x * x * x)));
}

// ---------------- reduce helpers ----------------
__device__ __forceinline__ float block_reduce_sum(float v, float* sh) {
    #pragma unroll
    for (int o = 16; o; o >>= 1) v += __shfl_xor_sync(0xffffffffu, v, o);
    int w = threadIdx.x >> 5;
    if ((threadIdx.x & 31) == 0) sh[w] = v;
    __syncthreads();
    if (threadIdx.x < 32) {
        float x = (threadIdx.x < (blockDim.x >> 5)) ? sh[threadIdx.x] : 0.f;
        #pragma unroll
        for (int o = 16; o; o >>= 1) x += __shfl_xor_sync(0xffffffffu, x, o);
        if (threadIdx.x == 0) sh[0] = x;
    }
    __syncthreads();
    return sh[0];
}
__device__ __forceinline__ float block_reduce_max(float v, float* sh) {
    #pragma unroll
    for (int o = 16; o; o >>= 1) v = fmaxf(v, __shfl_xor_sync(0xffffffffu, v, o));
    int w = threadIdx.x >> 5;
    if ((threadIdx.x & 31) == 0) sh[w] = v;
    __syncthreads();
    if (threadIdx.x < 32) {
        float x = (threadIdx.x < (blockDim.x >> 5)) ? sh[threadIdx.x] : -3.4e38f;
        #pragma unroll
        for (int o = 16; o; o >>= 1) x = fmaxf(x, __shfl_xor_sync(0xffffffffu, x, o));
        if (threadIdx.x == 0) sh[0] = x;
    }
    __syncthreads();
    return sh[0];
}

// ---------------- weight convert+transpose: W[K][N] f32 -> Wt[N][K] half ----------------
__global__ void __launch_bounds__(256) wt_kernel(const float* __restrict__ W,
                                                 __half* __restrict__ Wt,
                                                 int K, int N) {
    __shared__ float t[32][33];
    const int n0 = blockIdx.x * 32, k0 = blockIdx.y * 32;
    const int tid = threadIdx.x;
    #pragma unroll
    for (int r = 0; r < 4; r++) {
        int idx = tid + r * 256;
        int k = idx >> 5, n = idx & 31;
        t[k][n] = W[(size_t)(k0 + k) * N + n0 + n];
    }
    __syncthreads();
    int n = tid >> 3, kq = tid & 7;
    __half2 p0 = __floats2half2_rn(t[kq * 4 + 0][n], t[kq * 4 + 1][n]);
    __half2 p1 = __floats2half2_rn(t[kq * 4 + 2][n], t[kq * 4 + 3][n]);
    uint2 u = { *(unsigned*)&p0, *(unsigned*)&p1 };
    *(uint2*)&Wt[(size_t)(n0 + n) * K + k0 + kq * 4] = u;
}

// ================= fp16 NT GEMM: cp.async 3-stage + ldmatrix =================
// A: half [M][K] (k contig), B: half [N][K] (k contig). Block 128x128, BK=64.
// mode 0: alpha*AB(+bias); 1: gelu(AB+bias); 2: residual + gate[col]*(AB+bias)
__global__ void __launch_bounds__(256, 2) hgemm(const __half* __restrict__ A, int lda, long long sA,
                                                const __half* __restrict__ B, int ldb, long long sB,
                                                void* __restrict__ Cv, int ldc, long long sC, int c_half,
                                                int K, float alpha,
                                                const float* __restrict__ bias,
                                                const float* __restrict__ gate,
                                                const float* __restrict__ residual,
                                                int ldr, int mode) {
    extern __shared__ char smem[];
    const int tid  = threadIdx.x;
    const int warp = tid >> 5, lane = tid & 31;
    const int g = lane >> 2, tg = lane & 3;
    const int bm = blockIdx.x * 128, bn = blockIdx.y * 128;
    const int wm = (warp & 1) * 64, wn = (warp >> 1) * 32;

    A += (long long)blockIdx.z * sA + (long long)bm * lda;
    B += (long long)blockIdx.z * sB + (long long)bn * ldb;

    const uint32_t s0 = smem_u32(smem);
    const int cm = tid >> 3, ckh = tid & 7;

    const uint32_t a_off = (uint32_t)((wm + (lane & 7) + ((lane >> 3) & 1) * 8) * ROWB + (lane >> 4) * 16);
    const uint32_t b_off = (uint32_t)((wn + (lane & 7) + ((lane >> 4) & 1) * 8) * ROWB + ((lane >> 3) & 1) * 16);

    const int nch = K >> 6;

    // prologue: issue chunks 0 and 1
    #pragma unroll
    for (int c = 0; c < 2; c++) {
        if (c < nch) {
            const uint32_t sa = s0 + c * STAGEB, sb = sa + ABUF;
            const int k0 = c << 6;
            #pragma unroll
            for (int r = 0; r < 4; r++) {
                int m = cm + r * 32;
                cp16(sa + m * ROWB + ckh * 16, A + (long long)m * lda + k0 + ckh * 8);
                cp16(sb + m * ROWB + ckh * 16, B + (long long)m * ldb + k0 + ckh * 8);
            }
        }
        cp_commit();
    }

    float acc[4][4][4] = {};
    int st = 0, st2 = 2 % STAGES;
    for (int c = 0; c < nch; c++) {
        cp_wait1();            // chunk c resident
        __syncthreads();       // also: everyone done reading stage st2 (== chunk c-1's successor slot)

        // issue chunk c+2 into stage st2
        if (c + 2 < nch) {
            const uint32_t sa = s0 + st2 * STAGEB, sb = sa + ABUF;
            const int k0 = (c + 2) << 6;
            #pragma unroll
            for (int r = 0; r < 4; r++) {
                int m = cm + r * 32;
                cp16(sa + m * ROWB + ckh * 16, A + (long long)m * lda + k0 + ckh * 8);
                cp16(sb + m * ROWB + ckh * 16, B + (long long)m * ldb + k0 + ckh * 8);
            }
        }
        cp_commit();

        // compute chunk c from stage st
        const uint32_t ab = s0 + st * STAGEB + a_off;
        const uint32_t bb = s0 + st * STAGEB + ABUF + b_off;
        #pragma unroll
        for (int ks = 0; ks < 4; ks++) {
            unsigned af[4][4], bf[4][2];
            #pragma unroll
            for (int i = 0; i < 4; i++)
                ldm4(af[i], ab + i * (16 * ROWB) + ks * 32);
            #pragma unroll
            for (int jp = 0; jp < 2; jp++) {
                unsigned t4[4];
                ldm4(t4, bb + jp * (16 * ROWB) + ks * 32);
                bf[jp * 2][0] = t4[0]; bf[jp * 2][1] = t4[1];
                bf[jp * 2 + 1][0] = t4[2]; bf[jp * 2 + 1][1] = t4[3];
            }
            #pragma unroll
            for (int i = 0; i < 4; i++)
                #pragma unroll
                for (int j = 0; j < 4; j++)
                    mma_f16(acc[i][j], af[i], bf[j]);
        }
        st  = (st  + 1 == STAGES) ? 0 : st + 1;
        st2 = (st2 + 1 == STAGES) ? 0 : st2 + 1;
    }

    // ---- epilogue ----
    #pragma unroll
    for (int i = 0; i < 4; i++) {
        int r0 = bm + wm + i * 16 + g;
        #pragma unroll
        for (int j = 0; j < 4; j++) {
            int cc = bn + wn + j * 8 + 2 * tg;
            float v0 = acc[i][j][0] * alpha, v1 = acc[i][j][1] * alpha;
            float v2 = acc[i][j][2] * alpha, v3 = acc[i][j][3] * alpha;
            if (bias) {
                float b0 = bias[cc], b1 = bias[cc + 1];
                v0 += b0; v1 += b1; v2 += b0; v3 += b1;
            }
            if (mode == 1) {
                v0 = gelu_tanh(v0); v1 = gelu_tanh(v1);
                v2 = gelu_tanh(v2); v3 = gelu_tanh(v3);
            } else if (mode == 2) {
                const float* q0 = residual + (long long)r0 * ldr + cc;
                const float* q1 = residual + (long long)(r0 + 8) * ldr + cc;
                float g0 = gate[cc], g1 = gate[cc + 1];
                v0 = q0[0] + g0 * v0; v1 = q0[1] + g1 * v1;
                v2 = q1[0] + g0 * v2; v3 = q1[1] + g1 * v3;
            }
            if (c_half) {
                __half* C = (__half*)Cv + (long long)blockIdx.z * sC;
                *(__half2*)&C[(long long)r0 * ldc + cc]       = __floats2half2_rn(v0, v1);
                *(__half2*)&C[(long long)(r0 + 8) * ldc + cc] = __floats2half2_rn(v2, v3);
            } else {
                float* C = (float*)Cv + (long long)blockIdx.z * sC;
                float2 o0 = {v0, v1}, o1 = {v2, v3};
                *(float2*)&C[(long long)r0 * ldc + cc]       = o0;
                *(float2*)&C[(long long)(r0 + 8) * ldc + cc] = o1;
            }
        }
    }
}

// ---------------- modulation GEMV ----------------
__global__ void __launch_bounds__(256) mod_gemv(const float* __restrict__ vec,
                                                const float* __restrict__ w,
                                                const float* __restrict__ b,
                                                float* __restrict__ out) {
    __shared__ float sv[H];
    for (int i = threadIdx.x; i < H; i += 256) {
        float x = vec[i];
        sv[i] = x / (1.f + expf(-x));
    }
    __syncthreads();
    int col = blockIdx.x * 256 + threadIdx.x;
    float acc = b[col];
    const float* wp = w + col;
    #pragma unroll 8
    for (int i = 0; i < H; i++) acc += sv[i] * wp[(size_t)i * MOD6];
    out[col] = acc;
}

// ---------------- LayerNorm + modulate -> half ----------------
__global__ void __launch_bounds__(256) ln_mod_kernel(const float* __restrict__ x,
                                                     __half* __restrict__ y,
                                                     const float* __restrict__ sh,
                                                     const float* __restrict__ sc) {
    __shared__ float s0[32], s1[32];
    int row = blockIdx.x;
    const float* xr = x + (size_t)row * H;
    float s = 0.f, s2 = 0.f;
    for (int j = threadIdx.x; j < H; j += 256) {
        float v = xr[j];
        s += v; s2 += v * v;
    }
    float sum  = block_reduce_sum(s,  s0);
    float sum2 = block_reduce_sum(s2, s1);
    float mean = sum * (1.f / H);
    float var  = sum2 * (1.f / H) - mean * mean;
    float inv  = rsqrtf(var + 1e-6f);
    __half* yr = y + (size_t)row * H;
    for (int j = threadIdx.x * 2; j < H; j += 512) {
        float a = (xr[j]     - mean) * inv * (1.f + sc[j])     + sh[j];
        float b = (xr[j + 1] - mean) * inv * (1.f + sc[j + 1]) + sh[j + 1];
        *(__half2*)&yr[j] = __floats2half2_rn(a, b);
    }
}

// ---------------- QKV postprocess (half in) -> half q/k, half V^T ----------------
__global__ void __launch_bounds__(128) qkv_post_kernel(const __half* __restrict__ qkv,
                                                       const float* __restrict__ pe,
                                                       const float* __restrict__ nq_i,
                                                       const float* __restrict__ nk_i,
                                                       const float* __restrict__ nq_t,
                                                       const float* __restrict__ nk_t,
                                                       __half* __restrict__ gq,
                                                       __half* __restrict__ gk,
                                                       __half* __restrict__ gv) {
    int s = blockIdx.x, h = blockIdx.y, d = threadIdx.x;
    const __half* base = qkv + (size_t)s * QKV3 + h * HD;
    float qv = __half2float(base[d]);
    float kv = __half2float(base[H + d]);
    float vv = __half2float(base[2 * H + d]);
    float sq = qv * qv, sk = kv * kv;
    #pragma unroll
    for (int o = 16; o; o >>= 1) {
        sq += __shfl_xor_sync(0xffffffffu, sq, o);
        sk += __shfl_xor_sync(0xffffffffu, sk, o);
    }
    __shared__ float r0[4], r1[4];
    int w = d >> 5;
    if ((d & 31) == 0) { r0[w] = sq; r1[w] = sk; }
    __syncthreads();
    sq = r0[0] + r0[1] + r0[2] + r0[3];
    sk = r1[0] + r1[1] + r1[2] + r1[3];
    bool is_txt = s < LT;
    float qn = qv * rsqrtf(sq * (1.f / HD) + 1e-6f) * (is_txt ? nq_t[d] : nq_i[d]);
    float kn = kv * rsqrtf(sk * (1.f / HD) + 1e-6f) * (is_txt ? nk_t[d] : nk_i[d]);
    float qp = __shfl_xor_sync(0xffffffffu, qn, 1);
    float kp = __shfl_xor_sync(0xffffffffu, kn, 1);
    const float4 f = *reinterpret_cast<const float4*>(pe + ((size_t)s * 64 + (d >> 1)) * 4);
    float qo = (d & 1) ? (f.z * qp + f.w * qn) : (f.x * qn + f.y * qp);
    float ko = (d & 1) ? (f.z * kp + f.w * kn) : (f.x * kn + f.y * kp);
    size_t idx = ((size_t)h * L + s) * HD + d;
    gq[idx] = __float2half(qo);
    gk[idx] = __float2half(ko);
    gv[((size_t)h * HD + d) * L + s] = __float2half(vv);
}

// ---------------- softmax over half rows of S ----------------
__global__ void __launch_bounds__(256) softmax_rows(__half* __restrict__ S) {
    __shared__ float s0[32], s1[32];
    __half2* row = (__half2*)(S + (size_t)blockIdx.x * L);
    int t = threadIdx.x;
    float2 v[3];
    #pragma unroll
    for (int i = 0; i < 3; i++) v[i] = __half22float2(row[t + i * 256]);
    float m = fmaxf(fmaxf(fmaxf(v[0].x, v[0].y), fmaxf(v[1].x, v[1].y)), fmaxf(v[2].x, v[2].y));
    m = block_reduce_max(m, s0);
    float sum = 0.f;
    #pragma unroll
    for (int i = 0; i < 3; i++) {
        v[i].x = __expf(v[i].x - m); v[i].y = __expf(v[i].y - m);
        sum += v[i].x + v[i].y;
    }
    sum = block_reduce_sum(sum, s1);
    float inv = 1.f / sum;
    #pragma unroll
    for (int i = 0; i < 3; i++)
        row[t + i * 256] = __floats2half2_rn(v[i].x * inv, v[i].y * inv);
}

// ---------------- launch ----------------
extern "C" void kernel_launch(void* const* d_in, const int* in_sizes, int n_in,
                              void* d_out, int out_size) {
    const float* img      = (const float*)d_in[0];
    const float* txt      = (const float*)d_in[1];
    const float* vec      = (const float*)d_in[2];
    const float* pe       = (const float*)d_in[3];
    const float* mod_w    = (const float*)d_in[4];
    const float* mod_b    = (const float*)d_in[5];
    const float* qkv_w    = (const float*)d_in[6];
    const float* qkv_b    = (const float*)d_in[7];
    const float* norm_q_w = (const float*)d_in[8];
    const float* norm_k_w = (const float*)d_in[9];
    const float* out_w    = (const float*)d_in[10];
    const float* out_b    = (const float*)d_in[11];
    const float* fc1_w    = (const float*)d_in[12];
    const float* fc1_b    = (const float*)d_in[13];
    const float* fc2_w    = (const float*)d_in[14];
    const float* fc2_b    = (const float*)d_in[15];
    const float* mod_c_w  = (const float*)d_in[16];
    const float* mod_c_b  = (const float*)d_in[17];
    const float* qkv_c_w  = (const float*)d_in[18];
    const float* qkv_c_b  = (const float*)d_in[19];
    const float* norm_aq_w= (const float*)d_in[20];
    const float* norm_ak_w= (const float*)d_in[21];
    const float* out_c_w  = (const float*)d_in[22];
    const float* out_c_b  = (const float*)d_in[23];
    const float* fc1_c_w  = (const float*)d_in[24];
    const float* fc1_c_b  = (const float*)d_in[25];
    const float* fc2_c_w  = (const float*)d_in[26];
    const float* fc2_c_b  = (const float*)d_in[27];
    float* out = (float*)d_out;

    float *modi, *modt, *res2;
    __half *qkvh, *xmod, *qb, *kb, *vb, *Sb, *attnb, *hb, *fc1b;
    __half *qkvw_t, *qkvcw_t, *outw_t, *outcw_t, *fc1w_t, *fc1cw_t, *fc2w_t, *fc2cw_t;
    cudaGetSymbolAddress((void**)&modi,   g_mod_img);
    cudaGetSymbolAddress((void**)&modt,   g_mod_txt);
    cudaGetSymbolAddress((void**)&res2,   g_res2);
    cudaGetSymbolAddress((void**)&qkvh,   g_qkvh);
    cudaGetSymbolAddress((void**)&xmod,   g_xmod);
    cudaGetSymbolAddress((void**)&qb,     g_q);
    cudaGetSymbolAddress((void**)&kb,     g_k);
    cudaGetSymbolAddress((void**)&vb,     g_v);
    cudaGetSymbolAddress((void**)&Sb,     g_S);
    cudaGetSymbolAddress((void**)&attnb,  g_attn);
    cudaGetSymbolAddress((void**)&hb,     g_hbuf);
    cudaGetSymbolAddress((void**)&fc1b,   g_fc1);
    cudaGetSymbolAddress((void**)&qkvw_t, g_qkvw_t);
    cudaGetSymbolAddress((void**)&qkvcw_t,g_qkvcw_t);
    cudaGetSymbolAddress((void**)&outw_t, g_outw_t);
    cudaGetSymbolAddress((void**)&outcw_t,g_outcw_t);
    cudaGetSymbolAddress((void**)&fc1w_t, g_fc1w_t);
    cudaGetSymbolAddress((void**)&fc1cw_t,g_fc1cw_t);
    cudaGetSymbolAddress((void**)&fc2w_t, g_fc2w_t);
    cudaGetSymbolAddress((void**)&fc2cw_t,g_fc2cw_t);

    cudaFuncSetAttribute(hgemm, cudaFuncAttributeMaxDynamicSharedMemorySize, DSMEM);

    // 0) weight convert + transpose  W[K][N] -> Wt[N][K] half
    wt_kernel<<<dim3(QKV3/32, H/32), 256>>>(qkv_w,   qkvw_t,  H, QKV3);
    wt_kernel<<<dim3(QKV3/32, H/32), 256>>>(qkv_c_w, qkvcw_t, H, QKV3);
    wt_kernel<<<dim3(H/32,    H/32), 256>>>(out_w,   outw_t,  H, H);
    wt_kernel<<<dim3(H/32,    H/32), 256>>>(out_c_w, outcw_t, H, H);
    wt_kernel<<<dim3(MLPD/32, H/32), 256>>>(fc1_w,   fc1w_t,  H, MLPD);
    wt_kernel<<<dim3(MLPD/32, H/32), 256>>>(fc1_c_w, fc1cw_t, H, MLPD);
    wt_kernel<<<dim3(H/32, MLPD/32), 256>>>(fc2_w,   fc2w_t,  MLPD, H);
    wt_kernel<<<dim3(H/32, MLPD/32), 256>>>(fc2_c_w, fc2cw_t, MLPD, H);

    // 1) modulation vectors
    mod_gemv<<<MOD6 / 256, 256>>>(vec, mod_w,   mod_b,   modi);
    mod_gemv<<<MOD6 / 256, 256>>>(vec, mod_c_w, mod_c_b, modt);

    // 2) LN + modulate (stage 1) -> half [txt; img]
    ln_mod_kernel<<<LT, 256>>>(txt, xmod,                  modt, modt + H);
    ln_mod_kernel<<<LI, 256>>>(img, xmod + (size_t)LT * H, modi, modi + H);

    // 3) qkv GEMMs -> half qkvh
    hgemm<<<dim3(LT/128, QKV3/128, 1), 256, DSMEM>>>(
        xmod, H, 0, qkvcw_t, H, 0, qkvh, QKV3, 0, 1, H, 1.f,
        qkv_c_b, nullptr, nullptr, 0, 0);
    hgemm<<<dim3(LI/128, QKV3/128, 1), 256, DSMEM>>>(
        xmod + (size_t)LT * H, H, 0, qkvw_t, H, 0,
        qkvh + (size_t)LT * QKV3, QKV3, 0, 1, H, 1.f,
        qkv_b, nullptr, nullptr, 0, 0);

    // 4) rms + rope + head-major split (half)
    {
        dim3 g(L, NH);
        qkv_post_kernel<<<g, 128>>>(qkvh, pe, norm_q_w, norm_k_w, norm_aq_w, norm_ak_w,
                                    qb, kb, vb);
    }

    // 5) S = scale * Q K^T -> half Sb
    hgemm<<<dim3(L/128, L/128, NH), 256, DSMEM>>>(
        qb, HD, (long long)L * HD, kb, HD, (long long)L * HD,
        Sb, L, (long long)L * L, 1, HD, 0.08838834764831845f,
        nullptr, nullptr, nullptr, 0, 0);

    // 6) softmax (half)
    softmax_rows<<<NH * L, 256>>>(Sb);

    // 7) O = P @ V (B = V^T [d][l]) -> half attnb [L][H]
    hgemm<<<dim3(L/128, 1, NH), 256, DSMEM>>>(
        Sb, L, (long long)L * L, vb, L, (long long)HD * L,
        attnb, H, (long long)HD, 1, L, 1.f,
        nullptr, nullptr, nullptr, 0, 0);

    // 8) out projection + gated residual -> f32 res2
    hgemm<<<dim3(LT/128, H/128, 1), 256, DSMEM>>>(
        attnb, H, 0, outcw_t, H, 0, res2, H, 0, 0, H, 1.f,
        out_c_b, modt + 2 * H, txt, H, 2);
    hgemm<<<dim3(LI/128, H/128, 1), 256, DSMEM>>>(
        attnb + (size_t)LT * H, H, 0, outw_t, H, 0,
        res2 + (size_t)LT * H, H, 0, 0, H, 1.f,
        out_b, modi + 2 * H, img, H, 2);

    // 9) LN + modulate (stage 2) -> half hb
    ln_mod_kernel<<<LT, 256>>>(res2,                  hb,                  modt + 3 * H, modt + 4 * H);
    ln_mod_kernel<<<LI, 256>>>(res2 + (size_t)LT * H, hb + (size_t)LT * H, modi + 3 * H, modi + 4 * H);

    // 10) fc1 + gelu -> half fc1b
    hgemm<<<dim3(LT/128, MLPD/128, 1), 256, DSMEM>>>(
        hb, H, 0, fc1cw_t, H, 0, fc1b, MLPD, 0, 1, H, 1.f,
        fc1_c_b, nullptr, nullptr, 0, 1);
    hgemm<<<dim3(LI/128, MLPD/128, 1), 256, DSMEM>>>(
        hb + (size_t)LT * H, H, 0, fc1w_t, H, 0,
        fc1b + (size_t)LT * MLPD, MLPD, 0, 1, H, 1.f,
        fc1_b, nullptr, nullptr, 0, 1);

    // 11) fc2 + gated residual -> f32 final output (img first, then txt)
    hgemm<<<dim3(LT/128, H/128, 1), 256, DSMEM>>>(
        fc1b, MLPD, 0, fc2cw_t, MLPD, 0, out + (size_t)LI * H, H, 0, 0, MLPD, 1.f,
        fc2_c_b, modt + 5 * H, res2, H, 2);
    hgemm<<<dim3(LI/128, H/128, 1), 256, DSMEM>>>(
        fc1b + (size_t)LT * MLPD, MLPD, 0, fc2w_t, MLPD, 0, out, H, 0, 0, MLPD, 1.f,
        fc2_b, modi + 5 * H, res2 + (size_t)LT * H, H, 2);

    (void)in_sizes; (void)n_in; (void)out_size;
}

// round 10
// speedup vs baseline: 1.1945x; 1.1945x over previous
#include <cuda_runtime.h>
#include <cuda_fp16.h>
#include <math.h>
#include <stdint.h>

#define H    3072
#define NH   24
#define HD   128
#define MLPD 12288
#define LT   512
#define LI   1024
#define L    1536
#define QKV3 9216
#define MOD6 18432

#define ROWB   144
#define ABUF   (128 * ROWB)
#define DSMEM  (4 * ABUF)

// ---------------- scratch ----------------
__device__ float g_mod_img[MOD6];
__device__ float g_mod_txt[MOD6];
__device__ float g_res2[(size_t)L * H];
__device__ __align__(16) __half g_qkvh[(size_t)L * QKV3];
__device__ __align__(16) __half g_xmod[(size_t)L * H];
__device__ __align__(16) __half g_q   [(size_t)NH * L * HD];
__device__ __align__(16) __half g_k   [(size_t)NH * L * HD];
__device__ __align__(16) __half g_v   [(size_t)NH * HD * L];
__device__ __align__(16) __half g_S   [(size_t)NH * L * L];
__device__ __align__(16) __half g_attn[(size_t)L * H];
__device__ __align__(16) __half g_hbuf[(size_t)L * H];
__device__ __align__(16) __half g_fc1 [(size_t)L * MLPD];
__device__ __align__(16) __half g_qkvw_t [(size_t)QKV3 * H];
__device__ __align__(16) __half g_qkvcw_t[(size_t)QKV3 * H];
__device__ __align__(16) __half g_outw_t [(size_t)H * H];
__device__ __align__(16) __half g_outcw_t[(size_t)H * H];
__device__ __align__(16) __half g_fc1w_t [(size_t)MLPD * H];
__device__ __align__(16) __half g_fc1cw_t[(size_t)MLPD * H];
__device__ __align__(16) __half g_fc2w_t [(size_t)H * MLPD];
__device__ __align__(16) __half g_fc2cw_t[(size_t)H * MLPD];

// ---------------- ptx helpers ----------------
__device__ __forceinline__ uint32_t smem_u32(const void* p) {
    uint32_t a;
    asm("{ .reg .u64 t; cvta.to.shared.u64 t, %1; cvt.u32.u64 %0, t; }" : "=r"(a) : "l"(p));
    return a;
}
__device__ __forceinline__ void cp16(uint32_t dst, const void* src) {
    asm volatile("cp.async.cg.shared.global [%0], [%1], 16;" :: "r"(dst), "l"(src));
}
__device__ __forceinline__ void cp_commit() { asm volatile("cp.async.commit_group;"); }
__device__ __forceinline__ void cp_wait1()  { asm volatile("cp.async.wait_group 1;"); }
__device__ __forceinline__ void ldm4(unsigned* r, uint32_t a) {
    asm volatile("ldmatrix.sync.aligned.m8n8.x4.shared.b16 {%0,%1,%2,%3}, [%4];"
                 : "=r"(r[0]), "=r"(r[1]), "=r"(r[2]), "=r"(r[3]) : "r"(a));
}
__device__ __forceinline__ void mma_f16(float* c, const unsigned* a, const unsigned* b) {
    asm volatile(
        "mma.sync.aligned.m16n8k16.row.col.f32.f16.f16.f32 "
        "{%0,%1,%2,%3}, {%4,%5,%6,%7}, {%8,%9}, {%0,%1,%2,%3};\n"
        : "+f"(c[0]), "+f"(c[1]), "+f"(c[2]), "+f"(c[3])
        : "r"(a[0]), "r"(a[1]), "r"(a[2]), "r"(a[3]), "r"(b[0]), "r"(b[1]));
}
__device__ __forceinline__ float gelu_tanh(float x) {
    return 0.5f * x * (1.f + tanhf(0.7978845608028654f * (x + 0.044715f * x * x * x)));
}

// ---------------- reduce helpers ----------------
__device__ __forceinline__ float block_reduce_sum(float v, float* sh) {
    #pragma unroll
    for (int o = 16; o; o >>= 1) v += __shfl_xor_sync(0xffffffffu, v, o);
    int w = threadIdx.x >> 5;
    if ((threadIdx.x & 31) == 0) sh[w] = v;
    __syncthreads();
    if (threadIdx.x < 32) {
        float x = (threadIdx.x < (blockDim.x >> 5)) ? sh[threadIdx.x] : 0.f;
        #pragma unroll
        for (int o = 16; o; o >>= 1) x += __shfl_xor_sync(0xffffffffu, x, o);
        if (threadIdx.x == 0) sh[0] = x;
    }
    __syncthreads();
    return sh[0];
}
__device__ __forceinline__ float block_reduce_max(float v, float* sh) {
    #pragma unroll
    for (int o = 16; o; o >>= 1) v = fmaxf(v, __shfl_xor_sync(0xffffffffu, v, o));
    int w = threadIdx.x >> 5;
    if ((threadIdx.x & 31) == 0) sh[w] = v;
    __syncthreads();
    if (threadIdx.x < 32) {
        float x = (threadIdx.x < (blockDim.x >> 5)) ? sh[threadIdx.x] : -3.4e38f;
        #pragma unroll
        for (int o = 16; o; o >>= 1) x = fmaxf(x, __shfl_xor_sync(0xffffffffu, x, o));
        if (threadIdx.x == 0) sh[0] = x;
    }
    __syncthreads();
    return sh[0];
}

// ---------------- weight convert+transpose, coalesced 16B stores ----------------
// W[K][N] f32 -> Wt[N][K] half.  Tile: 64 k x 32 n per block.
__global__ void __launch_bounds__(256) wt_kernel(const float* __restrict__ W,
                                                 __half* __restrict__ Wt,
                                                 int K, int N) {
    __shared__ float t[64][33];
    const int n0 = blockIdx.x * 32;
    const int k0 = blockIdx.y * 64;
    const int tid = threadIdx.x;
    #pragma unroll
    for (int r = 0; r < 2; r++) {
        int idx = tid + r * 256;
        int k = idx >> 3, n4 = (idx & 7) * 4;
        float4 v = *(const float4*)&W[(size_t)(k0 + k) * N + n0 + n4];
        t[k][n4] = v.x; t[k][n4 + 1] = v.y; t[k][n4 + 2] = v.z; t[k][n4 + 3] = v.w;
    }
    __syncthreads();
    int n = tid >> 3, kq = (tid & 7) * 8;
    __half hv[8];
    #pragma unroll
    for (int i = 0; i < 8; i++) hv[i] = __float2half(t[kq + i][n]);
    *(uint4*)&Wt[(size_t)(n0 + n) * K + k0 + kq] = *(uint4*)hv;
}

// ================= fp16 NT GEMM: 2-stage cp.async + ldmatrix, dual-region =================
// Blocks with blockIdx.x >= mSplit use the *2 parameter set (img region).
__global__ void __launch_bounds__(256, 2) hgemm(const __half* __restrict__ A, int lda, long long sA,
                                                const __half* __restrict__ B, const __half* __restrict__ B2,
                                                int ldb, long long sB,
                                                void* __restrict__ Cv, void* __restrict__ Cv2,
                                                int ldc, long long sC, int c_half,
                                                int K, float alpha, int mSplit,
                                                const float* __restrict__ bias, const float* __restrict__ bias2,
                                                const float* __restrict__ gate, const float* __restrict__ gate2,
                                                const float* __restrict__ residual, const float* __restrict__ residual2,
                                                int ldr, int mode) {
    extern __shared__ char smem[];
    const int tid  = threadIdx.x;
    const int warp = tid >> 5, lane = tid & 31;
    const int g = lane >> 2, tg = lane & 3;
    const int bm = blockIdx.x * 128, bn = blockIdx.y * 128;
    const int wm = (warp & 1) * 64, wn = (warp >> 1) * 32;

    const bool second = (int)blockIdx.x >= mSplit;
    const __half* Bp = second ? B2 : B;
    const float* biasp = second ? bias2 : bias;
    const float* gatep = second ? gate2 : gate;
    const float* resp  = second ? residual2 : residual;
    void* Cp = second ? Cv2 : Cv;

    const __half* Ap = A + (long long)blockIdx.z * sA + (long long)bm * lda;
    Bp += (long long)blockIdx.z * sB + (long long)bn * ldb;

    const uint32_t sa = smem_u32(smem);
    const uint32_t sb = sa + 2 * ABUF;
    const int cm = tid >> 3, ckh = tid & 7;

    const uint32_t a_off = (uint32_t)((wm + (lane & 7) + ((lane >> 3) & 1) * 8) * ROWB + (lane >> 4) * 16);
    const uint32_t b_off = (uint32_t)((wn + (lane & 7) + ((lane >> 4) & 1) * 8) * ROWB + ((lane >> 3) & 1) * 16);

    const int nch = K >> 6;

    // prologue: issue chunk 0
    #pragma unroll
    for (int r = 0; r < 4; r++) {
        int m = cm + r * 32;
        cp16(sa + m * ROWB + ckh * 16, Ap + (long long)m * lda + ckh * 8);
        cp16(sb + m * ROWB + ckh * 16, Bp + (long long)m * ldb + ckh * 8);
    }
    cp_commit();

    float acc[4][4][4] = {};
    for (int c = 0; c < nch; c++) {
        const int p = c & 1;
        if (c + 1 < nch) {
            const int q = (c + 1) & 1;
            const int k0 = (c + 1) << 6;
            #pragma unroll
            for (int r = 0; r < 4; r++) {
                int m = cm + r * 32;
                cp16(sa + q * ABUF + m * ROWB + ckh * 16, Ap + (long long)m * lda + k0 + ckh * 8);
                cp16(sb + q * ABUF + m * ROWB + ckh * 16, Bp + (long long)m * ldb + k0 + ckh * 8);
            }
        }
        cp_commit();
        cp_wait1();
        __syncthreads();

        const uint32_t ab = sa + p * ABUF + a_off;
        const uint32_t bb = sb + p * ABUF + b_off;
        #pragma unroll
        for (int ks = 0; ks < 4; ks++) {
            unsigned af[4][4], bf[4][2];
            #pragma unroll
            for (int i = 0; i < 4; i++)
                ldm4(af[i], ab + i * (16 * ROWB) + ks * 32);
            #pragma unroll
            for (int jp = 0; jp < 2; jp++) {
                unsigned t4[4];
                ldm4(t4, bb + jp * (16 * ROWB) + ks * 32);
                bf[jp * 2][0] = t4[0]; bf[jp * 2][1] = t4[1];
                bf[jp * 2 + 1][0] = t4[2]; bf[jp * 2 + 1][1] = t4[3];
            }
            #pragma unroll
            for (int i = 0; i < 4; i++)
                #pragma unroll
                for (int j = 0; j < 4; j++)
                    mma_f16(acc[i][j], af[i], bf[j]);
        }
        __syncthreads();
    }

    // ---- epilogue ----
    #pragma unroll
    for (int i = 0; i < 4; i++) {
        int r0 = bm + wm + i * 16 + g;
        #pragma unroll
        for (int j = 0; j < 4; j++) {
            int cc = bn + wn + j * 8 + 2 * tg;
            float v0 = acc[i][j][0] * alpha, v1 = acc[i][j][1] * alpha;
            float v2 = acc[i][j][2] * alpha, v3 = acc[i][j][3] * alpha;
            if (biasp) {
                float b0 = biasp[cc], b1 = biasp[cc + 1];
                v0 += b0; v1 += b1; v2 += b0; v3 += b1;
            }
            if (mode == 1) {
                v0 = gelu_tanh(v0); v1 = gelu_tanh(v1);
                v2 = gelu_tanh(v2); v3 = gelu_tanh(v3);
            } else if (mode == 2) {
                const float* q0 = resp + (long long)r0 * ldr + cc;
                const float* q1 = resp + (long long)(r0 + 8) * ldr + cc;
                float g0 = gatep[cc], g1 = gatep[cc + 1];
                v0 = q0[0] + g0 * v0; v1 = q0[1] + g1 * v1;
                v2 = q1[0] + g0 * v2; v3 = q1[1] + g1 * v3;
            }
            if (c_half) {
                __half* C = (__half*)Cp + (long long)blockIdx.z * sC;
                *(__half2*)&C[(long long)r0 * ldc + cc]       = __floats2half2_rn(v0, v1);
                *(__half2*)&C[(long long)(r0 + 8) * ldc + cc] = __floats2half2_rn(v2, v3);
            } else {
                float* C = (float*)Cp + (long long)blockIdx.z * sC;
                float2 o0 = {v0, v1}, o1 = {v2, v3};
                *(float2*)&C[(long long)r0 * ldc + cc]       = o0;
                *(float2*)&C[(long long)(r0 + 8) * ldc + cc] = o1;
            }
        }
    }
}

// ---------------- modulation GEMV ----------------
__global__ void __launch_bounds__(256) mod_gemv(const float* __restrict__ vec,
                                                const float* __restrict__ w,
                                                const float* __restrict__ b,
                                                float* __restrict__ out) {
    __shared__ float sv[H];
    for (int i = threadIdx.x; i < H; i += 256) {
        float x = vec[i];
        sv[i] = x / (1.f + expf(-x));
    }
    __syncthreads();
    int col = blockIdx.x * 256 + threadIdx.x;
    float acc = b[col];
    const float* wp = w + col;
    #pragma unroll 8
    for (int i = 0; i < H; i++) acc += sv[i] * wp[(size_t)i * MOD6];
    out[col] = acc;
}

// ---------------- LayerNorm + modulate (dual-region) -> half ----------------
// rows [0,split) from x1 with sh1/sc1; rows >= split from x2 (pre-offset) with sh2/sc2.
__global__ void __launch_bounds__(256) ln_mod_kernel(const float* __restrict__ x1,
                                                     const float* __restrict__ x2,
                                                     int split,
                                                     __half* __restrict__ y,
                                                     const float* __restrict__ sh1,
                                                     const float* __restrict__ sc1,
                                                     const float* __restrict__ sh2,
                                                     const float* __restrict__ sc2) {
    __shared__ float s0[32], s1[32];
    int row = blockIdx.x;
    const bool sec = row >= split;
    const float* xr = (sec ? x2 : x1) + (size_t)row * H;
    const float* sh = sec ? sh2 : sh1;
    const float* sc = sec ? sc2 : sc1;
    float s = 0.f, s2 = 0.f;
    for (int j = threadIdx.x; j < H; j += 256) {
        float v = xr[j];
        s += v; s2 += v * v;
    }
    float sum  = block_reduce_sum(s,  s0);
    float sum2 = block_reduce_sum(s2, s1);
    float mean = sum * (1.f / H);
    float var  = sum2 * (1.f / H) - mean * mean;
    float inv  = rsqrtf(var + 1e-6f);
    __half* yr = y + (size_t)row * H;
    for (int j = threadIdx.x * 2; j < H; j += 512) {
        float a = (xr[j]     - mean) * inv * (1.f + sc[j])     + sh[j];
        float b = (xr[j + 1] - mean) * inv * (1.f + sc[j + 1]) + sh[j + 1];
        *(__half2*)&yr[j] = __floats2half2_rn(a, b);
    }
}

// ---------------- QKV postprocess (half in) -> half q/k, half V^T ----------------
__global__ void __launch_bounds__(128) qkv_post_kernel(const __half* __restrict__ qkv,
                                                       const float* __restrict__ pe,
                                                       const float* __restrict__ nq_i,
                                                       const float* __restrict__ nk_i,
                                                       const float* __restrict__ nq_t,
                                                       const float* __restrict__ nk_t,
                                                       __half* __restrict__ gq,
                                                       __half* __restrict__ gk,
                                                       __half* __restrict__ gv) {
    int s = blockIdx.x, h = blockIdx.y, d = threadIdx.x;
    const __half* base = qkv + (size_t)s * QKV3 + h * HD;
    float qv = __half2float(base[d]);
    float kv = __half2float(base[H + d]);
    float vv = __half2float(base[2 * H + d]);
    float sq = qv * qv, sk = kv * kv;
    #pragma unroll
    for (int o = 16; o; o >>= 1) {
        sq += __shfl_xor_sync(0xffffffffu, sq, o);
        sk += __shfl_xor_sync(0xffffffffu, sk, o);
    }
    __shared__ float r0[4], r1[4];
    int w = d >> 5;
    if ((d & 31) == 0) { r0[w] = sq; r1[w] = sk; }
    __syncthreads();
    sq = r0[0] + r0[1] + r0[2] + r0[3];
    sk = r1[0] + r1[1] + r1[2] + r1[3];
    bool is_txt = s < LT;
    float qn = qv * rsqrtf(sq * (1.f / HD) + 1e-6f) * (is_txt ? nq_t[d] : nq_i[d]);
    float kn = kv * rsqrtf(sk * (1.f / HD) + 1e-6f) * (is_txt ? nk_t[d] : nk_i[d]);
    float qp = __shfl_xor_sync(0xffffffffu, qn, 1);
    float kp = __shfl_xor_sync(0xffffffffu, kn, 1);
    const float4 f = *reinterpret_cast<const float4*>(pe + ((size_t)s * 64 + (d >> 1)) * 4);
    float qo = (d & 1) ? (f.z * qp + f.w * qn) : (f.x * qn + f.y * qp);
    float ko = (d & 1) ? (f.z * kp + f.w * kn) : (f.x * kn + f.y * kp);
    size_t idx = ((size_t)h * L + s) * HD + d;
    gq[idx] = __float2half(qo);
    gk[idx] = __float2half(ko);
    gv[((size_t)h * HD + d) * L + s] = __float2half(vv);
}

// ---------------- softmax over half rows of S ----------------
__global__ void __launch_bounds__(256) softmax_rows(__half* __restrict__ S) {
    __shared__ float s0[32], s1[32];
    __half2* row = (__half2*)(S + (size_t)blockIdx.x * L);
    int t = threadIdx.x;
    float2 v[3];
    #pragma unroll
    for (int i = 0; i < 3; i++) v[i] = __half22float2(row[t + i * 256]);
    float m = fmaxf(fmaxf(fmaxf(v[0].x, v[0].y), fmaxf(v[1].x, v[1].y)), fmaxf(v[2].x, v[2].y));
    m = block_reduce_max(m, s0);
    float sum = 0.f;
    #pragma unroll
    for (int i = 0; i < 3; i++) {
        v[i].x = __expf(v[i].x - m); v[i].y = __expf(v[i].y - m);
        sum += v[i].x + v[i].y;
    }
    sum = block_reduce_sum(sum, s1);
    float inv = 1.f / sum;
    #pragma unroll
    for (int i = 0; i < 3; i++)
        row[t + i * 256] = __floats2half2_rn(v[i].x * inv, v[i].y * inv);
}

// ---------------- launch ----------------
extern "C" void kernel_launch(void* const* d_in, const int* in_sizes, int n_in,
                              void* d_out, int out_size) {
    const float* img      = (const float*)d_in[0];
    const float* txt      = (const float*)d_in[1];
    const float* vec      = (const float*)d_in[2];
    const float* pe       = (const float*)d_in[3];
    const float* mod_w    = (const float*)d_in[4];
    const float* mod_b    = (const float*)d_in[5];
    const float* qkv_w    = (const float*)d_in[6];
    const float* qkv_b    = (const float*)d_in[7];
    const float* norm_q_w = (const float*)d_in[8];
    const float* norm_k_w = (const float*)d_in[9];
    const float* out_w    = (const float*)d_in[10];
    const float* out_b    = (const float*)d_in[11];
    const float* fc1_w    = (const float*)d_in[12];
    const float* fc1_b    = (const float*)d_in[13];
    const float* fc2_w    = (const float*)d_in[14];
    const float* fc2_b    = (const float*)d_in[15];
    const float* mod_c_w  = (const float*)d_in[16];
    const float* mod_c_b  = (const float*)d_in[17];
    const float* qkv_c_w  = (const float*)d_in[18];
    const float* qkv_c_b  = (const float*)d_in[19];
    const float* norm_aq_w= (const float*)d_in[20];
    const float* norm_ak_w= (const float*)d_in[21];
    const float* out_c_w  = (const float*)d_in[22];
    const float* out_c_b  = (const float*)d_in[23];
    const float* fc1_c_w  = (const float*)d_in[24];
    const float* fc1_c_b  = (const float*)d_in[25];
    const float* fc2_c_w  = (const float*)d_in[26];
    const float* fc2_c_b  = (const float*)d_in[27];
    float* out = (float*)d_out;

    float *modi, *modt, *res2;
    __half *qkvh, *xmod, *qb, *kb, *vb, *Sb, *attnb, *hb, *fc1b;
    __half *qkvw_t, *qkvcw_t, *outw_t, *outcw_t, *fc1w_t, *fc1cw_t, *fc2w_t, *fc2cw_t;
    cudaGetSymbolAddress((void**)&modi,   g_mod_img);
    cudaGetSymbolAddress((void**)&modt,   g_mod_txt);
    cudaGetSymbolAddress((void**)&res2,   g_res2);
    cudaGetSymbolAddress((void**)&qkvh,   g_qkvh);
    cudaGetSymbolAddress((void**)&xmod,   g_xmod);
    cudaGetSymbolAddress((void**)&qb,     g_q);
    cudaGetSymbolAddress((void**)&kb,     g_k);
    cudaGetSymbolAddress((void**)&vb,     g_v);
    cudaGetSymbolAddress((void**)&Sb,     g_S);
    cudaGetSymbolAddress((void**)&attnb,  g_attn);
    cudaGetSymbolAddress((void**)&hb,     g_hbuf);
    cudaGetSymbolAddress((void**)&fc1b,   g_fc1);
    cudaGetSymbolAddress((void**)&qkvw_t, g_qkvw_t);
    cudaGetSymbolAddress((void**)&qkvcw_t,g_qkvcw_t);
    cudaGetSymbolAddress((void**)&outw_t, g_outw_t);
    cudaGetSymbolAddress((void**)&outcw_t,g_outcw_t);
    cudaGetSymbolAddress((void**)&fc1w_t, g_fc1w_t);
    cudaGetSymbolAddress((void**)&fc1cw_t,g_fc1cw_t);
    cudaGetSymbolAddress((void**)&fc2w_t, g_fc2w_t);
    cudaGetSymbolAddress((void**)&fc2cw_t,g_fc2cw_t);

    cudaFuncSetAttribute(hgemm, cudaFuncAttributeMaxDynamicSharedMemorySize, DSMEM);

    const int BIG = 1 << 30;
    // pre-offset img pointers so a GLOBAL row index >= 512 lands at img row (row-512)
    const float* img_off = img - (size_t)LT * H;
    float* out_img_off = out - (size_t)LT * H;          // img rows -> out[0..]
    float* out_txt     = out + (size_t)LI * H;          // txt rows 0..511 -> out + LI*H

    // 0) weight convert + transpose (coalesced): grid (N/32, K/64)
    wt_kernel<<<dim3(QKV3/32, H/64), 256>>>(qkv_w,   qkvw_t,  H, QKV3);
    wt_kernel<<<dim3(QKV3/32, H/64), 256>>>(qkv_c_w, qkvcw_t, H, QKV3);
    wt_kernel<<<dim3(H/32,    H/64), 256>>>(out_w,   outw_t,  H, H);
    wt_kernel<<<dim3(H/32,    H/64), 256>>>(out_c_w, outcw_t, H, H);
    wt_kernel<<<dim3(MLPD/32, H/64), 256>>>(fc1_w,   fc1w_t,  H, MLPD);
    wt_kernel<<<dim3(MLPD/32, H/64), 256>>>(fc1_c_w, fc1cw_t, H, MLPD);
    wt_kernel<<<dim3(H/32, MLPD/64), 256>>>(fc2_w,   fc2w_t,  MLPD, H);
    wt_kernel<<<dim3(H/32, MLPD/64), 256>>>(fc2_c_w, fc2cw_t, MLPD, H);

    // 1) modulation vectors
    mod_gemv<<<MOD6 / 256, 256>>>(vec, mod_w,   mod_b,   modi);
    mod_gemv<<<MOD6 / 256, 256>>>(vec, mod_c_w, mod_c_b, modt);

    // 2) LN + modulate stage 1 (merged) -> half xmod [txt; img]
    ln_mod_kernel<<<L, 256>>>(txt, img_off, LT, xmod,
                              modt, modt + H, modi, modi + H);

    // 3) qkv GEMM (merged txt/img) -> half qkvh
    hgemm<<<dim3(L/128, QKV3/128, 1), 256, DSMEM>>>(
        xmod, H, 0, qkvcw_t, qkvw_t, H, 0,
        qkvh, qkvh, QKV3, 0, 1, H, 1.f, LT/128,
        qkv_c_b, qkv_b, nullptr, nullptr, nullptr, nullptr, 0, 0);

    // 4) rms + rope + head-major split
    {
        dim3 g(L, NH);
        qkv_post_kernel<<<g, 128>>>(qkvh, pe, norm_q_w, norm_k_w, norm_aq_w, norm_ak_w,
                                    qb, kb, vb);
    }

    // 5) S = scale * Q K^T
    hgemm<<<dim3(L/128, L/128, NH), 256, DSMEM>>>(
        qb, HD, (long long)L * HD, kb, kb, HD, (long long)L * HD,
        Sb, Sb, L, (long long)L * L, 1, HD, 0.08838834764831845f, BIG,
        nullptr, nullptr, nullptr, nullptr, nullptr, nullptr, 0, 0);

    // 6) softmax
    softmax_rows<<<NH * L, 256>>>(Sb);

    // 7) O = P @ V -> half attnb [L][H]
    hgemm<<<dim3(L/128, 1, NH), 256, DSMEM>>>(
        Sb, L, (long long)L * L, vb, vb, L, (long long)HD * L,
        attnb, attnb, H, (long long)HD, 1, L, 1.f, BIG,
        nullptr, nullptr, nullptr, nullptr, nullptr, nullptr, 0, 0);

    // 8) out projection + gated residual (merged) -> f32 res2 [txt; img]
    hgemm<<<dim3(L/128, H/128, 1), 256, DSMEM>>>(
        attnb, H, 0, outcw_t, outw_t, H, 0,
        res2, res2, H, 0, 0, H, 1.f, LT/128,
        out_c_b, out_b, modt + 2 * H, modi + 2 * H, txt, img_off, H, 2);

    // 9) LN + modulate stage 2 (merged) -> half hb
    ln_mod_kernel<<<L, 256>>>(res2, res2, LT, hb,
                              modt + 3 * H, modt + 4 * H, modi + 3 * H, modi + 4 * H);

    // 10) fc1 + gelu (merged) -> half fc1b
    hgemm<<<dim3(L/128, MLPD/128, 1), 256, DSMEM>>>(
        hb, H, 0, fc1cw_t, fc1w_t, H, 0,
        fc1b, fc1b, MLPD, 0, 1, H, 1.f, LT/128,
        fc1_c_b, fc1_b, nullptr, nullptr, nullptr, nullptr, 0, 1);

    // 11) fc2 + gated residual (merged) -> f32 final output
    hgemm<<<dim3(L/128, H/128, 1), 256, DSMEM>>>(
        fc1b, MLPD, 0, fc2cw_t, fc2w_t, MLPD, 0,
        out_txt, out_img_off, H, 0, 0, MLPD, 1.f, LT/128,
        fc2_c_b, fc2_b, modt + 5 * H, modi + 5 * H, res2, res2, H, 2);

    (void)in_sizes; (void)n_in; (void)out_size;
}